// round 2
// baseline (speedup 1.0000x reference)
#include <cuda_runtime.h>

#define BB 2048
#define TT 128
#define NN 64
#define HH 128
#define G4 512   // 4*H
#define MM 8     // batches per CTA

// ---------------- device scratch (allocation-free: __device__ globals) -------
__device__ __align__(16) float g_prex[BB * NN * HH];   // [b][n][k]  67 MB
__device__ __align__(16) float g_WhsT[256 * HH];       // [j][k]   j<128: W1_h col, j>=128: W1_s col
__device__ __align__(16) float g_W1xT[TT * HH];        // [t][k]
__device__ __align__(16) float g_WihG[NN * G4];        // [n][q*4+gate]
__device__ __align__(16) float g_WhhG[HH * G4];        // [j][q*4+gate]
__device__ __align__(16) float g_bG[G4];               // [q*4+gate]

__device__ __forceinline__ float tanh_fast(float x) {
    float y; asm("tanh.approx.f32 %0, %1;" : "=f"(y) : "f"(x)); return y;
}
__device__ __forceinline__ float sigmoid_f(float x) {
    return 1.0f / (1.0f + __expf(-x));
}
__device__ __forceinline__ void fma4(float4& a, float s, const float4 w) {
    a.x = fmaf(s, w.x, a.x); a.y = fmaf(s, w.y, a.y);
    a.z = fmaf(s, w.z, a.z); a.w = fmaf(s, w.w, a.w);
}

// ---------------- kernel 0: weight layout prep --------------------------------
__global__ void prep_kernel(const float* __restrict__ W_attn1,
                            const float* __restrict__ W_ih,
                            const float* __restrict__ W_hh,
                            const float* __restrict__ b_ih,
                            const float* __restrict__ b_hh)
{
    int tid = blockIdx.x * blockDim.x + threadIdx.x;
    int nt  = gridDim.x * blockDim.x;
    // WhsT[j*128+k] = W_attn1[k*384 + j]   (covers both W1_h (j<128) and W1_s (j in [128,256)))
    for (int i = tid; i < 256 * HH; i += nt) {
        int j = i >> 7, k = i & 127;
        g_WhsT[i] = W_attn1[k * 384 + j];
    }
    // W1xT[t*128+k] = W_attn1[k*384 + 256 + t]
    for (int i = tid; i < TT * HH; i += nt) {
        int t = i >> 7, k = i & 127;
        g_W1xT[i] = W_attn1[k * 384 + 256 + t];
    }
    // WihG[n*512 + q*4+g] = W_ih[(g*128+q)*64 + n]
    for (int i = tid; i < NN * G4; i += nt) {
        int n = i >> 9, r = i & 511, q = r >> 2, g = r & 3;
        g_WihG[i] = W_ih[(g * HH + q) * NN + n];
    }
    // WhhG[j*512 + q*4+g] = W_hh[(g*128+q)*128 + j]
    for (int i = tid; i < HH * G4; i += nt) {
        int j = i >> 9, r = i & 511, q = r >> 2, g = r & 3;
        g_WhhG[i] = W_hh[(g * HH + q) * HH + j];
    }
    for (int i = tid; i < G4; i += nt) {
        int q = i >> 2, g = i & 3;
        g_bG[i] = b_ih[g * HH + q] + b_hh[g * HH + q];
    }
}

// ---------------- kernel 1: pre_x[b][n][k] = sum_t X[b][t][n]*W1x[k][t] + b1[k]
__global__ __launch_bounds__(256) void prex_kernel(const float* __restrict__ X,
                                                   const float* __restrict__ b_attn1)
{
    __shared__ float sX[TT * NN];   // [t][n]  32 KB
    int b = blockIdx.x;
    int tid = threadIdx.x;
    const float* Xb = X + (size_t)b * TT * NN;
    for (int i = tid; i < TT * NN; i += 256) sX[i] = Xb[i];
    __syncthreads();

    const float4* W4  = (const float4*)g_W1xT;     // [t][32 quads]
    const float4* b14 = (const float4*)b_attn1;
    float4* out4 = (float4*)(g_prex + (size_t)b * NN * HH);

    for (int qi = tid; qi < NN * 32; qi += 256) {
        int n = qi >> 5, kq = qi & 31;
        float4 acc = b14[kq];
        #pragma unroll 4
        for (int t = 0; t < TT; ++t) {
            float x = sX[t * NN + n];
            fma4(acc, x, W4[t * 32 + kq]);
        }
        out4[n * 32 + kq] = acc;
    }
}

// ---------------- kernel 2: the recurrence ------------------------------------
__global__ __launch_bounds__(256, 2) void rnn_kernel(
    const float* __restrict__ X,
    const float* __restrict__ w_attn2,
    const float* __restrict__ b_attn2,
    float* __restrict__ out)
{
    __shared__ __align__(16) float s_hc[MM][256];  // [m][0:128]=h, [128:256]=c
    __shared__ __align__(16) float s_u [MM][HH];
    __shared__ float s_e [MM][NN];
    __shared__ float s_xt[MM][NN];

    int tid  = threadIdx.x;
    int lane = tid & 31;
    int warp = tid >> 5;            // warp == m for phases (a)(b)(c)
    int b0   = blockIdx.x * MM;

    float  b2  = b_attn2[0];
    float4 w2v = ((const float4*)w_attn2)[lane];   // k = lane*4..+3

    // zero initial state
    for (int i = tid; i < MM * 256; i += 256) ((float*)s_hc)[i] = 0.0f;

    // thread mapping for gates/update
    int q = tid & 127, grp = tid >> 7;
    int mb = grp * 4;
    const float4* WhsT4 = (const float4*)g_WhsT;   // [j][32]
    const float4* WhhG4 = (const float4*)g_WhhG;   // [j][128]
    const float4* WihG4 = (const float4*)g_WihG;   // [n][128]
    const float4* prex4 = (const float4*)g_prex;
    float4 bg = ((const float4*)g_bG)[q];
    __syncthreads();

    for (int t = 0; t < TT; ++t) {
        // ---- (a) u[m][k] = sum_j [h|c][m][j] * WhsT[j][k] ; warp=m, k=lane*4..+3
        {
            int m = warp;
            float4 acc = make_float4(0.f, 0.f, 0.f, 0.f);
            #pragma unroll 4
            for (int j = 0; j < 256; ++j) {
                float sj = s_hc[m][j];                  // broadcast
                fma4(acc, sj, WhsT4[j * 32 + lane]);    // coalesced, L1-hot
            }
            ((float4*)s_u[m])[lane] = acc;
        }
        __syncthreads();

        // ---- (b) e[m][n] = b2 + sum_k w2[k]*tanh(prex[m][n][k] + u[m][k])
        {
            int m = warp;
            float4 uv = ((const float4*)s_u[m])[lane];
            const float4* pr = prex4 + (size_t)(b0 + m) * NN * 32;
            #pragma unroll 2
            for (int n = 0; n < NN; ++n) {
                float4 p = pr[n * 32 + lane];           // coalesced 512B/warp
                float z0 = tanh_fast(p.x + uv.x);
                float z1 = tanh_fast(p.y + uv.y);
                float z2 = tanh_fast(p.z + uv.z);
                float z3 = tanh_fast(p.w + uv.w);
                float part = z0 * w2v.x + z1 * w2v.y + z2 * w2v.z + z3 * w2v.w;
                #pragma unroll
                for (int off = 16; off > 0; off >>= 1)
                    part += __shfl_xor_sync(0xffffffffu, part, off);
                if (lane == 0) s_e[m][n] = part + b2;
            }
        }
        __syncthreads();

        // ---- (c) softmax over n (64) + x_tilde ; warp=m, 2 n per lane
        {
            int m = warp;
            float e0 = s_e[m][lane], e1 = s_e[m][lane + 32];
            float mx = fmaxf(e0, e1);
            #pragma unroll
            for (int off = 16; off > 0; off >>= 1)
                mx = fmaxf(mx, __shfl_xor_sync(0xffffffffu, mx, off));
            float x0 = __expf(e0 - mx), x1 = __expf(e1 - mx);
            float sum = x0 + x1;
            #pragma unroll
            for (int off = 16; off > 0; off >>= 1)
                sum += __shfl_xor_sync(0xffffffffu, sum, off);
            float inv = 1.0f / sum;
            const float* Xr = X + ((size_t)(b0 + m) * TT + t) * NN;
            s_xt[m][lane]      = x0 * inv * Xr[lane];
            s_xt[m][lane + 32] = x1 * inv * Xr[lane + 32];
        }
        __syncthreads();

        // ---- (d) gates[m][{i,f,g,o} at q] for m = mb..mb+3
        float4 acc0 = bg, acc1 = bg, acc2 = bg, acc3 = bg;
        #pragma unroll 2
        for (int j = 0; j < HH; ++j) {
            float4 w = WhhG4[j * 128 + q];              // coalesced, shared by both grps
            float h0 = s_hc[mb + 0][j];
            float h1 = s_hc[mb + 1][j];
            float h2 = s_hc[mb + 2][j];
            float h3 = s_hc[mb + 3][j];
            fma4(acc0, h0, w); fma4(acc1, h1, w);
            fma4(acc2, h2, w); fma4(acc3, h3, w);
        }
        #pragma unroll 2
        for (int n = 0; n < NN; ++n) {
            float4 w = WihG4[n * 128 + q];
            float x0 = s_xt[mb + 0][n];
            float x1 = s_xt[mb + 1][n];
            float x2 = s_xt[mb + 2][n];
            float x3 = s_xt[mb + 3][n];
            fma4(acc0, x0, w); fma4(acc1, x1, w);
            fma4(acc2, x2, w); fma4(acc3, x3, w);
        }

        // ---- (e) LSTM update (reads of old state done before the sync)
        float hn[4], cn[4];
        #pragma unroll
        for (int mm = 0; mm < 4; ++mm) {
            float4 a = (mm == 0) ? acc0 : (mm == 1) ? acc1 : (mm == 2) ? acc2 : acc3;
            float iv = sigmoid_f(a.x);
            float fv = sigmoid_f(a.y);
            float gv = tanhf(a.z);           // accurate in the recurrent path
            float ov = sigmoid_f(a.w);
            float cold = s_hc[mb + mm][128 + q];
            float c2 = fv * cold + iv * gv;
            cn[mm] = c2;
            hn[mm] = ov * tanhf(c2);
        }
        __syncthreads();   // all reads of old h/c complete
        #pragma unroll
        for (int mm = 0; mm < 4; ++mm) {
            s_hc[mb + mm][q]       = hn[mm];
            s_hc[mb + mm][128 + q] = cn[mm];
            out[((size_t)(b0 + mb + mm) * TT + t) * HH + q] = hn[mm];
        }
        __syncthreads();   // new state visible for next step's (a)
    }
}

// ---------------- launch ------------------------------------------------------
extern "C" void kernel_launch(void* const* d_in, const int* in_sizes, int n_in,
                              void* d_out, int out_size) {
    const float* X       = (const float*)d_in[0];
    const float* W_attn1 = (const float*)d_in[1];
    const float* b_attn1 = (const float*)d_in[2];
    const float* w_attn2 = (const float*)d_in[3];
    const float* b_attn2 = (const float*)d_in[4];
    const float* W_ih    = (const float*)d_in[5];
    const float* W_hh    = (const float*)d_in[6];
    const float* b_ih    = (const float*)d_in[7];
    const float* b_hh    = (const float*)d_in[8];
    float* out = (float*)d_out;

    prep_kernel<<<64, 256>>>(W_attn1, W_ih, W_hh, b_ih, b_hh);
    prex_kernel<<<BB, 256>>>(X, b_attn1);
    rnn_kernel<<<BB / MM, 256>>>(X, w_attn2, b_attn2, out);
}

// round 3
// speedup vs baseline: 1.0010x; 1.0010x over previous
#include <cuda_runtime.h>

#define BB 2048
#define TT 128
#define NN 64
#define HH 128
#define G4 512   // 4*H
#define MM 8     // batches per CTA

// ---------------- device scratch (allocation-free: __device__ globals) -------
__device__ __align__(16) float g_prex[BB * NN * HH];   // [b][n][k]  67 MB
__device__ __align__(16) float g_WhsT[256 * HH];       // [j][k]   j<128: W1_h col, j>=128: W1_s col
__device__ __align__(16) float g_W1xT[TT * HH];        // [t][k]
__device__ __align__(16) float g_WihG[NN * G4];        // [n][q*4+gate]
__device__ __align__(16) float g_WhhG[HH * G4];        // [j][q*4+gate]
__device__ __align__(16) float g_bG[G4];               // [q*4+gate]

__device__ __forceinline__ float tanh_fast(float x) {
    float y; asm("tanh.approx.f32 %0, %1;" : "=f"(y) : "f"(x)); return y;
}
__device__ __forceinline__ float sigmoid_f(float x) {
    return 1.0f / (1.0f + __expf(-x));
}
__device__ __forceinline__ void fma4(float4& a, float s, const float4 w) {
    a.x = fmaf(s, w.x, a.x); a.y = fmaf(s, w.y, a.y);
    a.z = fmaf(s, w.z, a.z); a.w = fmaf(s, w.w, a.w);
}

// ---------------- kernel 0: weight layout prep --------------------------------
__global__ void prep_kernel(const float* __restrict__ W_attn1,
                            const float* __restrict__ W_ih,
                            const float* __restrict__ W_hh,
                            const float* __restrict__ b_ih,
                            const float* __restrict__ b_hh)
{
    int tid = blockIdx.x * blockDim.x + threadIdx.x;
    int nt  = gridDim.x * blockDim.x;
    // WhsT[j*128+k] = W_attn1[k*384 + j]   (covers both W1_h (j<128) and W1_s (j in [128,256)))
    for (int i = tid; i < 256 * HH; i += nt) {
        int j = i >> 7, k = i & 127;
        g_WhsT[i] = W_attn1[k * 384 + j];
    }
    // W1xT[t*128+k] = W_attn1[k*384 + 256 + t]
    for (int i = tid; i < TT * HH; i += nt) {
        int t = i >> 7, k = i & 127;
        g_W1xT[i] = W_attn1[k * 384 + 256 + t];
    }
    // WihG[n*512 + q*4+g] = W_ih[(g*128+q)*64 + n]
    for (int i = tid; i < NN * G4; i += nt) {
        int n = i >> 9, r = i & 511, q = r >> 2, g = r & 3;
        g_WihG[i] = W_ih[(g * HH + q) * NN + n];
    }
    // WhhG[j*512 + q*4+g] = W_hh[(g*128+q)*128 + j]
    for (int i = tid; i < HH * G4; i += nt) {
        int j = i >> 9, r = i & 511, q = r >> 2, g = r & 3;
        g_WhhG[i] = W_hh[(g * HH + q) * HH + j];
    }
    for (int i = tid; i < G4; i += nt) {
        int q = i >> 2, g = i & 3;
        g_bG[i] = b_ih[g * HH + q] + b_hh[g * HH + q];
    }
}

// ---------------- kernel 1: pre_x[b][n][k] = sum_t X[b][t][n]*W1x[k][t] + b1[k]
__global__ __launch_bounds__(256) void prex_kernel(const float* __restrict__ X,
                                                   const float* __restrict__ b_attn1)
{
    __shared__ float sX[TT * NN];   // [t][n]  32 KB
    int b = blockIdx.x;
    int tid = threadIdx.x;
    const float* Xb = X + (size_t)b * TT * NN;
    for (int i = tid; i < TT * NN; i += 256) sX[i] = Xb[i];
    __syncthreads();

    const float4* W4  = (const float4*)g_W1xT;     // [t][32 quads]
    const float4* b14 = (const float4*)b_attn1;
    float4* out4 = (float4*)(g_prex + (size_t)b * NN * HH);

    for (int qi = tid; qi < NN * 32; qi += 256) {
        int n = qi >> 5, kq = qi & 31;
        float4 acc = b14[kq];
        #pragma unroll 4
        for (int t = 0; t < TT; ++t) {
            float x = sX[t * NN + n];
            fma4(acc, x, W4[t * 32 + kq]);
        }
        out4[n * 32 + kq] = acc;
    }
}

// ---------------- kernel 2: the recurrence ------------------------------------
__global__ __launch_bounds__(256, 2) void rnn_kernel(
    const float* __restrict__ X,
    const float* __restrict__ w_attn2,
    const float* __restrict__ b_attn2,
    float* __restrict__ out)
{
    __shared__ __align__(16) float s_hc[MM][256];  // [m][0:128]=h, [128:256]=c
    __shared__ __align__(16) float s_u [MM][HH];
    __shared__ float s_e [MM][NN];
    __shared__ float s_xt[MM][NN];

    int tid  = threadIdx.x;
    int lane = tid & 31;
    int warp = tid >> 5;            // warp == m for phases (a)(b)(c)
    int b0   = blockIdx.x * MM;

    float  b2  = b_attn2[0];
    float4 w2v = ((const float4*)w_attn2)[lane];   // k = lane*4..+3

    // zero initial state
    for (int i = tid; i < MM * 256; i += 256) ((float*)s_hc)[i] = 0.0f;

    // thread mapping for gates/update
    int q = tid & 127, grp = tid >> 7;
    int mb = grp * 4;
    const float4* WhsT4 = (const float4*)g_WhsT;   // [j][32]
    const float4* WhhG4 = (const float4*)g_WhhG;   // [j][128]
    const float4* WihG4 = (const float4*)g_WihG;   // [n][128]
    const float4* prex4 = (const float4*)g_prex;
    float4 bg = ((const float4*)g_bG)[q];
    __syncthreads();

    for (int t = 0; t < TT; ++t) {
        // ---- (a) u[m][k] = sum_j [h|c][m][j] * WhsT[j][k] ; warp=m, k=lane*4..+3
        {
            int m = warp;
            float4 acc = make_float4(0.f, 0.f, 0.f, 0.f);
            #pragma unroll 4
            for (int j = 0; j < 256; ++j) {
                float sj = s_hc[m][j];                  // broadcast
                fma4(acc, sj, WhsT4[j * 32 + lane]);    // coalesced, L1-hot
            }
            ((float4*)s_u[m])[lane] = acc;
        }
        __syncthreads();

        // ---- (b) e[m][n] = b2 + sum_k w2[k]*tanh(prex[m][n][k] + u[m][k])
        {
            int m = warp;
            float4 uv = ((const float4*)s_u[m])[lane];
            const float4* pr = prex4 + (size_t)(b0 + m) * NN * 32;
            #pragma unroll 2
            for (int n = 0; n < NN; ++n) {
                float4 p = pr[n * 32 + lane];           // coalesced 512B/warp
                float z0 = tanh_fast(p.x + uv.x);
                float z1 = tanh_fast(p.y + uv.y);
                float z2 = tanh_fast(p.z + uv.z);
                float z3 = tanh_fast(p.w + uv.w);
                float part = z0 * w2v.x + z1 * w2v.y + z2 * w2v.z + z3 * w2v.w;
                #pragma unroll
                for (int off = 16; off > 0; off >>= 1)
                    part += __shfl_xor_sync(0xffffffffu, part, off);
                if (lane == 0) s_e[m][n] = part + b2;
            }
        }
        __syncthreads();

        // ---- (c) softmax over n (64) + x_tilde ; warp=m, 2 n per lane
        {
            int m = warp;
            float e0 = s_e[m][lane], e1 = s_e[m][lane + 32];
            float mx = fmaxf(e0, e1);
            #pragma unroll
            for (int off = 16; off > 0; off >>= 1)
                mx = fmaxf(mx, __shfl_xor_sync(0xffffffffu, mx, off));
            float x0 = __expf(e0 - mx), x1 = __expf(e1 - mx);
            float sum = x0 + x1;
            #pragma unroll
            for (int off = 16; off > 0; off >>= 1)
                sum += __shfl_xor_sync(0xffffffffu, sum, off);
            float inv = 1.0f / sum;
            const float* Xr = X + ((size_t)(b0 + m) * TT + t) * NN;
            s_xt[m][lane]      = x0 * inv * Xr[lane];
            s_xt[m][lane + 32] = x1 * inv * Xr[lane + 32];
        }
        __syncthreads();

        // ---- (d) gates[m][{i,f,g,o} at q] for m = mb..mb+3
        float4 acc0 = bg, acc1 = bg, acc2 = bg, acc3 = bg;
        #pragma unroll 2
        for (int j = 0; j < HH; ++j) {
            float4 w = WhhG4[j * 128 + q];              // coalesced, shared by both grps
            float h0 = s_hc[mb + 0][j];
            float h1 = s_hc[mb + 1][j];
            float h2 = s_hc[mb + 2][j];
            float h3 = s_hc[mb + 3][j];
            fma4(acc0, h0, w); fma4(acc1, h1, w);
            fma4(acc2, h2, w); fma4(acc3, h3, w);
        }
        #pragma unroll 2
        for (int n = 0; n < NN; ++n) {
            float4 w = WihG4[n * 128 + q];
            float x0 = s_xt[mb + 0][n];
            float x1 = s_xt[mb + 1][n];
            float x2 = s_xt[mb + 2][n];
            float x3 = s_xt[mb + 3][n];
            fma4(acc0, x0, w); fma4(acc1, x1, w);
            fma4(acc2, x2, w); fma4(acc3, x3, w);
        }

        // ---- (e) LSTM update (reads of old state done before the sync)
        float hn[4], cn[4];
        #pragma unroll
        for (int mm = 0; mm < 4; ++mm) {
            float4 a = (mm == 0) ? acc0 : (mm == 1) ? acc1 : (mm == 2) ? acc2 : acc3;
            float iv = sigmoid_f(a.x);
            float fv = sigmoid_f(a.y);
            float gv = tanhf(a.z);           // accurate in the recurrent path
            float ov = sigmoid_f(a.w);
            float cold = s_hc[mb + mm][128 + q];
            float c2 = fv * cold + iv * gv;
            cn[mm] = c2;
            hn[mm] = ov * tanhf(c2);
        }
        __syncthreads();   // all reads of old h/c complete
        #pragma unroll
        for (int mm = 0; mm < 4; ++mm) {
            s_hc[mb + mm][q]       = hn[mm];
            s_hc[mb + mm][128 + q] = cn[mm];
            out[((size_t)(b0 + mb + mm) * TT + t) * HH + q] = hn[mm];
        }
        __syncthreads();   // new state visible for next step's (a)
    }
}

// ---------------- launch ------------------------------------------------------
extern "C" void kernel_launch(void* const* d_in, const int* in_sizes, int n_in,
                              void* d_out, int out_size) {
    const float* X       = (const float*)d_in[0];
    const float* W_attn1 = (const float*)d_in[1];
    const float* b_attn1 = (const float*)d_in[2];
    const float* w_attn2 = (const float*)d_in[3];
    const float* b_attn2 = (const float*)d_in[4];
    const float* W_ih    = (const float*)d_in[5];
    const float* W_hh    = (const float*)d_in[6];
    const float* b_ih    = (const float*)d_in[7];
    const float* b_hh    = (const float*)d_in[8];
    float* out = (float*)d_out;

    prep_kernel<<<64, 256>>>(W_attn1, W_ih, W_hh, b_ih, b_hh);
    prex_kernel<<<BB, 256>>>(X, b_attn1);
    rnn_kernel<<<BB / MM, 256>>>(X, w_attn2, b_attn2, out);
}

// round 4
// speedup vs baseline: 1.4720x; 1.4705x over previous
#include <cuda_runtime.h>
#include <cuda_bf16.h>

#define BB 2048
#define TT 128
#define NN 64
#define HH 128
#define G4 512   // 4*H
#define MM 16    // batches per CTA
#define THR 512  // threads per CTA (16 warps)

// ---------------- device scratch (allocation-free: __device__ globals) -------
__device__ __align__(16) __nv_bfloat16 g_prex_bf[(size_t)BB * NN * HH]; // [b][n][k] bf16, 33 MB
__device__ __align__(16) float g_WhsT[256 * HH];   // [j][k] j<128: W1_h col, j>=128: W1_s col
__device__ __align__(16) float g_W1xT[TT * HH];    // [t][k]
__device__ __align__(16) float g_WihG[NN * G4];    // [n][q*4+gate]
__device__ __align__(16) float g_WhhG[HH * G4];    // [j][q*4+gate]
__device__ __align__(16) float g_bG[G4];           // [q*4+gate]

typedef unsigned long long ull;

__device__ __forceinline__ ull pk2(float a, float b) {
    ull r; asm("mov.b64 %0,{%1,%2};" : "=l"(r) : "f"(a), "f"(b)); return r;
}
__device__ __forceinline__ void fma2(ull& d, ull a, ull b) {
    asm("fma.rn.f32x2 %0, %1, %2, %0;" : "+l"(d) : "l"(a), "l"(b));
}
__device__ __forceinline__ float2 up2(ull v) {
    float2 r; asm("mov.b64 {%0,%1},%2;" : "=f"(r.x), "=f"(r.y) : "l"(v)); return r;
}
__device__ __forceinline__ float tanh_fast(float x) {
    float y; asm("tanh.approx.f32 %0, %1;" : "=f"(y) : "f"(x)); return y;
}
__device__ __forceinline__ float sigmoid_f(float x) {
    return 1.0f / (1.0f + __expf(-x));
}
__device__ __forceinline__ void fma4(float4& a, float s, const float4 w) {
    a.x = fmaf(s, w.x, a.x); a.y = fmaf(s, w.y, a.y);
    a.z = fmaf(s, w.z, a.z); a.w = fmaf(s, w.w, a.w);
}

// ---------------- kernel 0: weight layout prep --------------------------------
__global__ void prep_kernel(const float* __restrict__ W_attn1,
                            const float* __restrict__ W_ih,
                            const float* __restrict__ W_hh,
                            const float* __restrict__ b_ih,
                            const float* __restrict__ b_hh)
{
    int tid = blockIdx.x * blockDim.x + threadIdx.x;
    int nt  = gridDim.x * blockDim.x;
    for (int i = tid; i < 256 * HH; i += nt) {
        int j = i >> 7, k = i & 127;
        g_WhsT[i] = W_attn1[k * 384 + j];
    }
    for (int i = tid; i < TT * HH; i += nt) {
        int t = i >> 7, k = i & 127;
        g_W1xT[i] = W_attn1[k * 384 + 256 + t];
    }
    for (int i = tid; i < NN * G4; i += nt) {
        int n = i >> 9, r = i & 511, q = r >> 2, g = r & 3;
        g_WihG[i] = W_ih[(g * HH + q) * NN + n];
    }
    for (int i = tid; i < HH * G4; i += nt) {
        int j = i >> 9, r = i & 511, q = r >> 2, g = r & 3;
        g_WhhG[i] = W_hh[(g * HH + q) * HH + j];
    }
    for (int i = tid; i < G4; i += nt) {
        int q = i >> 2, g = i & 3;
        g_bG[i] = b_ih[g * HH + q] + b_hh[g * HH + q];
    }
}

// ---------------- kernel 1: pre_x[b][n][k] = sum_t X[b][t][n]*W1x[k][t] + b1[k]
// output bf16
__global__ __launch_bounds__(256) void prex_kernel(const float* __restrict__ X,
                                                   const float* __restrict__ b_attn1)
{
    __shared__ float sX[TT * NN];   // 32 KB
    int b = blockIdx.x;
    int tid = threadIdx.x;
    const float* Xb = X + (size_t)b * TT * NN;
    for (int i = tid; i < TT * NN; i += 256) sX[i] = Xb[i];
    __syncthreads();

    const float4* W4  = (const float4*)g_W1xT;     // [t][32 quads]
    const float4* b14 = (const float4*)b_attn1;
    uint2* out2 = (uint2*)(g_prex_bf + (size_t)b * NN * HH);

    for (int qi = tid; qi < NN * 32; qi += 256) {
        int n = qi >> 5, kq = qi & 31;
        float4 acc = b14[kq];
        #pragma unroll 4
        for (int t = 0; t < TT; ++t) {
            float x = sX[t * NN + n];
            fma4(acc, x, W4[t * 32 + kq]);
        }
        __nv_bfloat162 c0 = __floats2bfloat162_rn(acc.x, acc.y);
        __nv_bfloat162 c1 = __floats2bfloat162_rn(acc.z, acc.w);
        uint2 st;
        st.x = *(unsigned*)&c0;
        st.y = *(unsigned*)&c1;
        out2[n * 32 + kq] = st;
    }
}

// ---------------- kernel 2: the recurrence ------------------------------------
// dynamic smem layout (floats):
//   sW   [256*128] = 32768   (W_attn1^T, fp32)
//   hcA  [16*256]  = 4096    (double buffer A: [m][0:128]=h, [128:256]=c)
//   hcB  [16*256]  = 4096
//   sU   [16*128]  = 2048
//   sE4  [16*64*4] = 4096
//   sXT  [16*64]   = 1024
// total 48128 floats = 188 KB
#define SMEM_FLOATS 48128

__global__ __launch_bounds__(THR, 1) void rnn_kernel(
    const float* __restrict__ X,
    const float* __restrict__ w_attn2,
    const float* __restrict__ b_attn2,
    float* __restrict__ out)
{
    extern __shared__ float smem[];
    float* sW  = smem;
    float* hcA = sW + 32768;
    float* hcB = hcA + 4096;
    float* sU  = hcB + 4096;
    float* sE4 = sU + 2048;
    float* sXT = sE4 + 4096;

    int tid = threadIdx.x;
    int l = tid & 31;
    int w = tid >> 5;                 // warp id == m for phases (b)(c)
    size_t b0 = (size_t)blockIdx.x * MM;

    // stage W_attn1^T into smem (once)
    {
        const float4* src = (const float4*)g_WhsT;
        float4* dst = (float4*)sW;
        #pragma unroll 4
        for (int i = tid; i < 8192; i += THR) dst[i] = src[i];
    }
    for (int i = tid; i < 4096; i += THR) hcA[i] = 0.0f;   // zero initial state

    float  b2  = b_attn2[0];
    float4 w2v = ((const float4*)w_attn2)[l];

    // phase (a) mapping: warp w -> batchgrp bg (4 batches), k-group kg (32 k)
    int bgA = w >> 2, kgA = w & 3;
    int mA  = bgA * 4 + (l >> 3);          // batch this lane accumulates
    int kqA = kgA * 8 + (l & 7);           // k-quad this lane accumulates

    // phase (d) mapping
    int q = tid & 127, grp = tid >> 7, mb = grp * 4;
    float4 bgq = ((const float4*)g_bG)[q];
    ull bLo = pk2(bgq.x, bgq.y), bHi = pk2(bgq.z, bgq.w);

    const ulonglong2* Whh2 = (const ulonglong2*)g_WhhG;  // [j][64 pairs-of-2] at q
    const ulonglong2* Wih2 = (const ulonglong2*)g_WihG;
    const uint2* prb = (const uint2*)g_prex_bf + (size_t)(b0 + w) * 2048; // warp=m

    __syncthreads();

    for (int t = 0; t < TT; ++t) {
        float* hc  = (t & 1) ? hcB : hcA;
        float* hcn = (t & 1) ? hcA : hcB;

        // ---- (a) u[m][k] = sum_j [h|c][m][j] * WhsT[j][k]  (weights in smem)
        {
            const float4* hcm4 = (const float4*)(hc + mA * 256);
            const ulonglong2* sW2 = (const ulonglong2*)sW;   // [j][16]
            ull a0 = 0ull, a1 = 0ull;
            #pragma unroll 4
            for (int j4 = 0; j4 < 64; ++j4) {
                float4 hv = hcm4[j4];
                #pragma unroll
                for (int jj = 0; jj < 4; ++jj) {
                    ulonglong2 wv = sW2[(size_t)(j4 * 4 + jj) * 16 + kqA * 2 / 2
                                        ]; // placeholder, fixed below
                    (void)wv;
                    break;
                }
                // real body (indexing spelled out):
                {
                    float h0 = hv.x, h1 = hv.y, h2 = hv.z, h3 = hv.w;
                    ulonglong2 w0 = ((const ulonglong2*)sW)[(j4 * 4 + 0) * 32 + kqA];
                    ulonglong2 w1 = ((const ulonglong2*)sW)[(j4 * 4 + 1) * 32 + kqA];
                    ulonglong2 w2 = ((const ulonglong2*)sW)[(j4 * 4 + 2) * 32 + kqA];
                    ulonglong2 w3 = ((const ulonglong2*)sW)[(j4 * 4 + 3) * 32 + kqA];
                    ull p0 = pk2(h0, h0), p1 = pk2(h1, h1);
                    ull p2 = pk2(h2, h2), p3 = pk2(h3, h3);
                    fma2(a0, p0, w0.x); fma2(a1, p0, w0.y);
                    fma2(a0, p1, w1.x); fma2(a1, p1, w1.y);
                    fma2(a0, p2, w2.x); fma2(a1, p2, w2.y);
                    fma2(a0, p3, w3.x); fma2(a1, p3, w3.y);
                }
            }
            float2 r0 = up2(a0), r1 = up2(a1);
            ((float4*)(sU + mA * 128))[kqA] = make_float4(r0.x, r0.y, r1.x, r1.y);
        }
        __syncthreads();

        // ---- (b) partial e: warp=m; lane owns k-quad l; 3-level shuffle reduce
        {
            int m = w;
            float4 uv = ((const float4*)(sU + m * 128))[l];
            #pragma unroll 4
            for (int n = 0; n < NN; ++n) {
                uint2 pp = prb[n * 32 + l];   // 4 bf16 (k = l*4..l*4+3)
                float2 p01 = __bfloat1622float2(*(const __nv_bfloat162*)&pp.x);
                float2 p23 = __bfloat1622float2(*(const __nv_bfloat162*)&pp.y);
                float z0 = tanh_fast(p01.x + uv.x);
                float z1 = tanh_fast(p01.y + uv.y);
                float z2 = tanh_fast(p23.x + uv.z);
                float z3 = tanh_fast(p23.y + uv.w);
                float part = z0 * w2v.x + z1 * w2v.y + z2 * w2v.z + z3 * w2v.w;
                part += __shfl_xor_sync(0xffffffffu, part, 1);
                part += __shfl_xor_sync(0xffffffffu, part, 2);
                part += __shfl_xor_sync(0xffffffffu, part, 4);
                if ((l & 7) == 0) sE4[(m * 64 + n) * 4 + (l >> 3)] = part;
            }
        }
        __syncwarp();

        // ---- (c) finish e, softmax over n (64), x_tilde ; warp=m, 2 n per lane
        {
            int m = w;
            const float* e4 = sE4 + m * 256;
            float e0 = e4[l * 4 + 0] + e4[l * 4 + 1] + e4[l * 4 + 2] + e4[l * 4 + 3] + b2;
            int l2 = l + 32;
            float e1 = e4[l2 * 4 + 0] + e4[l2 * 4 + 1] + e4[l2 * 4 + 2] + e4[l2 * 4 + 3] + b2;
            float mx = fmaxf(e0, e1);
            #pragma unroll
            for (int o = 16; o > 0; o >>= 1)
                mx = fmaxf(mx, __shfl_xor_sync(0xffffffffu, mx, o));
            float x0 = __expf(e0 - mx), x1 = __expf(e1 - mx);
            float s = x0 + x1;
            #pragma unroll
            for (int o = 16; o > 0; o >>= 1)
                s += __shfl_xor_sync(0xffffffffu, s, o);
            float inv = 1.0f / s;
            const float* Xr = X + ((size_t)(b0 + m) * TT + t) * NN;
            sXT[m * 64 + l]      = x0 * inv * Xr[l];
            sXT[m * 64 + l + 32] = x1 * inv * Xr[l + 32];
        }
        __syncthreads();

        // ---- (d) gates for 4 batches mb..mb+3 at gate-quad q (f32x2 packed)
        ull aL0 = bLo, aH0 = bHi, aL1 = bLo, aH1 = bHi;
        ull aL2 = bLo, aH2 = bHi, aL3 = bLo, aH3 = bHi;
        {
            const float4* h40 = (const float4*)(hc + (mb + 0) * 256);
            const float4* h41 = (const float4*)(hc + (mb + 1) * 256);
            const float4* h42 = (const float4*)(hc + (mb + 2) * 256);
            const float4* h43 = (const float4*)(hc + (mb + 3) * 256);
            #pragma unroll 2
            for (int j4 = 0; j4 < 32; ++j4) {
                float4 v0 = h40[j4], v1 = h41[j4], v2 = h42[j4], v3 = h43[j4];
                #pragma unroll
                for (int jj = 0; jj < 4; ++jj) {
                    ulonglong2 wv = Whh2[(size_t)(j4 * 4 + jj) * 128 + q];
                    float f0 = (jj == 0) ? v0.x : (jj == 1) ? v0.y : (jj == 2) ? v0.z : v0.w;
                    float f1 = (jj == 0) ? v1.x : (jj == 1) ? v1.y : (jj == 2) ? v1.z : v1.w;
                    float f2 = (jj == 0) ? v2.x : (jj == 1) ? v2.y : (jj == 2) ? v2.z : v2.w;
                    float f3 = (jj == 0) ? v3.x : (jj == 1) ? v3.y : (jj == 2) ? v3.z : v3.w;
                    ull p0 = pk2(f0, f0), p1 = pk2(f1, f1);
                    ull p2 = pk2(f2, f2), p3 = pk2(f3, f3);
                    fma2(aL0, p0, wv.x); fma2(aH0, p0, wv.y);
                    fma2(aL1, p1, wv.x); fma2(aH1, p1, wv.y);
                    fma2(aL2, p2, wv.x); fma2(aH2, p2, wv.y);
                    fma2(aL3, p3, wv.x); fma2(aH3, p3, wv.y);
                }
            }
            const float4* x40 = (const float4*)(sXT + (mb + 0) * 64);
            const float4* x41 = (const float4*)(sXT + (mb + 1) * 64);
            const float4* x42 = (const float4*)(sXT + (mb + 2) * 64);
            const float4* x43 = (const float4*)(sXT + (mb + 3) * 64);
            #pragma unroll 2
            for (int n4 = 0; n4 < 16; ++n4) {
                float4 v0 = x40[n4], v1 = x41[n4], v2 = x42[n4], v3 = x43[n4];
                #pragma unroll
                for (int jj = 0; jj < 4; ++jj) {
                    ulonglong2 wv = Wih2[(size_t)(n4 * 4 + jj) * 128 + q];
                    float f0 = (jj == 0) ? v0.x : (jj == 1) ? v0.y : (jj == 2) ? v0.z : v0.w;
                    float f1 = (jj == 0) ? v1.x : (jj == 1) ? v1.y : (jj == 2) ? v1.z : v1.w;
                    float f2 = (jj == 0) ? v2.x : (jj == 1) ? v2.y : (jj == 2) ? v2.z : v2.w;
                    float f3 = (jj == 0) ? v3.x : (jj == 1) ? v3.y : (jj == 2) ? v3.z : v3.w;
                    ull p0 = pk2(f0, f0), p1 = pk2(f1, f1);
                    ull p2 = pk2(f2, f2), p3 = pk2(f3, f3);
                    fma2(aL0, p0, wv.x); fma2(aH0, p0, wv.y);
                    fma2(aL1, p1, wv.x); fma2(aH1, p1, wv.y);
                    fma2(aL2, p2, wv.x); fma2(aH2, p2, wv.y);
                    fma2(aL3, p3, wv.x); fma2(aH3, p3, wv.y);
                }
            }
        }

        // ---- (e) LSTM pointwise update -> double-buffered state + output
        #pragma unroll
        for (int mm = 0; mm < 4; ++mm) {
            ull aL = (mm == 0) ? aL0 : (mm == 1) ? aL1 : (mm == 2) ? aL2 : aL3;
            ull aH = (mm == 0) ? aH0 : (mm == 1) ? aH1 : (mm == 2) ? aH2 : aH3;
            float2 gif = up2(aL);   // i, f
            float2 ggo = up2(aH);   // g, o
            float iv = sigmoid_f(gif.x);
            float fv = sigmoid_f(gif.y);
            float gv = tanhf(ggo.x);
            float ov = sigmoid_f(ggo.y);
            float cold = hc[(mb + mm) * 256 + 128 + q];
            float c2 = fv * cold + iv * gv;
            float hn = ov * tanhf(c2);
            hcn[(mb + mm) * 256 + q]       = hn;
            hcn[(mb + mm) * 256 + 128 + q] = c2;
            out[((size_t)(b0 + mb + mm) * TT + t) * HH + q] = hn;
        }
        __syncthreads();   // hcn visible for next step's (a)/(d)
    }
}

// ---------------- launch ------------------------------------------------------
extern "C" void kernel_launch(void* const* d_in, const int* in_sizes, int n_in,
                              void* d_out, int out_size) {
    const float* X       = (const float*)d_in[0];
    const float* W_attn1 = (const float*)d_in[1];
    const float* b_attn1 = (const float*)d_in[2];
    const float* w_attn2 = (const float*)d_in[3];
    const float* b_attn2 = (const float*)d_in[4];
    const float* W_ih    = (const float*)d_in[5];
    const float* W_hh    = (const float*)d_in[6];
    const float* b_ih    = (const float*)d_in[7];
    const float* b_hh    = (const float*)d_in[8];
    float* out = (float*)d_out;

    cudaFuncSetAttribute(rnn_kernel, cudaFuncAttributeMaxDynamicSharedMemorySize,
                         SMEM_FLOATS * (int)sizeof(float));

    prep_kernel<<<64, 256>>>(W_attn1, W_ih, W_hh, b_ih, b_hh);
    prex_kernel<<<BB, 256>>>(X, b_attn1);
    rnn_kernel<<<BB / MM, THR, SMEM_FLOATS * sizeof(float)>>>(X, w_attn2, b_attn2, out);
}

// round 5
// speedup vs baseline: 1.4745x; 1.0017x over previous
#include <cuda_runtime.h>
#include <cuda_bf16.h>

#define BB 2048
#define TT 128
#define NN 64
#define HH 128
#define G4 512   // 4*H
#define MM 16    // batches per CTA
#define THR 512  // threads per CTA (16 warps)

// ---------------- device scratch (allocation-free: __device__ globals) -------
__device__ __align__(16) __nv_bfloat16 g_prex_bf[(size_t)BB * NN * HH]; // [b][n][k] bf16, 33 MB
__device__ __align__(16) float g_WhsT[256 * HH];   // [j][k] j<128: W1_h col, j>=128: W1_s col
__device__ __align__(16) float g_W1xT[TT * HH];    // [t][k]
__device__ __align__(16) float g_WihG[NN * G4];    // [n][q*4+gate]
__device__ __align__(16) float g_WhhG[HH * G4];    // [j][q*4+gate]
__device__ __align__(16) float g_bG[G4];           // [q*4+gate]

typedef unsigned long long ull;

__device__ __forceinline__ ull pk2(float a, float b) {
    ull r; asm("mov.b64 %0,{%1,%2};" : "=l"(r) : "f"(a), "f"(b)); return r;
}
__device__ __forceinline__ void fma2(ull& d, ull a, ull b) {
    asm("fma.rn.f32x2 %0, %1, %2, %0;" : "+l"(d) : "l"(a), "l"(b));
}
__device__ __forceinline__ float2 up2(ull v) {
    float2 r; asm("mov.b64 {%0,%1},%2;" : "=f"(r.x), "=f"(r.y) : "l"(v)); return r;
}
__device__ __forceinline__ float tanh_fast(float x) {
    float y; asm("tanh.approx.f32 %0, %1;" : "=f"(y) : "f"(x)); return y;
}
__device__ __forceinline__ float sigmoid_f(float x) {
    return 1.0f / (1.0f + __expf(-x));
}
__device__ __forceinline__ void fma4(float4& a, float s, const float4 w) {
    a.x = fmaf(s, w.x, a.x); a.y = fmaf(s, w.y, a.y);
    a.z = fmaf(s, w.z, a.z); a.w = fmaf(s, w.w, a.w);
}

// ---------------- kernel 0: weight layout prep --------------------------------
__global__ void prep_kernel(const float* __restrict__ W_attn1,
                            const float* __restrict__ W_ih,
                            const float* __restrict__ W_hh,
                            const float* __restrict__ b_ih,
                            const float* __restrict__ b_hh)
{
    int tid = blockIdx.x * blockDim.x + threadIdx.x;
    int nt  = gridDim.x * blockDim.x;
    for (int i = tid; i < 256 * HH; i += nt) {
        int j = i >> 7, k = i & 127;
        g_WhsT[i] = W_attn1[k * 384 + j];
    }
    for (int i = tid; i < TT * HH; i += nt) {
        int t = i >> 7, k = i & 127;
        g_W1xT[i] = W_attn1[k * 384 + 256 + t];
    }
    for (int i = tid; i < NN * G4; i += nt) {
        int n = i >> 9, r = i & 511, q = r >> 2, g = r & 3;
        g_WihG[i] = W_ih[(g * HH + q) * NN + n];
    }
    for (int i = tid; i < HH * G4; i += nt) {
        int j = i >> 9, r = i & 511, q = r >> 2, g = r & 3;
        g_WhhG[i] = W_hh[(g * HH + q) * HH + j];
    }
    for (int i = tid; i < G4; i += nt) {
        int q = i >> 2, g = i & 3;
        g_bG[i] = b_ih[g * HH + q] + b_hh[g * HH + q];
    }
}

// ---------------- kernel 1: pre_x[b][n][k] = sum_t X[b][t][n]*W1x[k][t] + b1[k]
// output bf16
__global__ __launch_bounds__(256) void prex_kernel(const float* __restrict__ X,
                                                   const float* __restrict__ b_attn1)
{
    __shared__ float sX[TT * NN];   // 32 KB
    int b = blockIdx.x;
    int tid = threadIdx.x;
    const float* Xb = X + (size_t)b * TT * NN;
    for (int i = tid; i < TT * NN; i += 256) sX[i] = Xb[i];
    __syncthreads();

    const float4* W4  = (const float4*)g_W1xT;     // [t][32 quads]
    const float4* b14 = (const float4*)b_attn1;
    uint2* out2 = (uint2*)(g_prex_bf + (size_t)b * NN * HH);

    for (int qi = tid; qi < NN * 32; qi += 256) {
        int n = qi >> 5, kq = qi & 31;
        float4 acc = b14[kq];
        #pragma unroll 4
        for (int t = 0; t < TT; ++t) {
            float x = sX[t * NN + n];
            fma4(acc, x, W4[t * 32 + kq]);
        }
        __nv_bfloat162 c0 = __floats2bfloat162_rn(acc.x, acc.y);
        __nv_bfloat162 c1 = __floats2bfloat162_rn(acc.z, acc.w);
        uint2 st;
        st.x = *(unsigned*)&c0;
        st.y = *(unsigned*)&c1;
        out2[n * 32 + kq] = st;
    }
}

// ---------------- kernel 2: the recurrence ------------------------------------
// dynamic smem layout (floats):
//   sW   [256*128] = 32768   (W_attn1^T, fp32)
//   hcA  [16*256]  = 4096    (double buffer A: [m][0:128]=h, [128:256]=c)
//   hcB  [16*256]  = 4096
//   sU   [16*128]  = 2048
//   sE4  [16*64*4] = 4096
//   sXT  [16*64]   = 1024
// total 48128 floats = 188 KB
#define SMEM_FLOATS 48128

__global__ __launch_bounds__(THR, 1) void rnn_kernel(
    const float* __restrict__ X,
    const float* __restrict__ w_attn2,
    const float* __restrict__ b_attn2,
    float* __restrict__ out)
{
    extern __shared__ float smem[];
    float* sW  = smem;
    float* hcA = sW + 32768;
    float* hcB = hcA + 4096;
    float* sU  = hcB + 4096;
    float* sE4 = sU + 2048;
    float* sXT = sE4 + 4096;

    int tid = threadIdx.x;
    int l = tid & 31;
    int w = tid >> 5;                 // warp id == m for phases (b)(c)
    size_t b0 = (size_t)blockIdx.x * MM;

    // stage W_attn1^T into smem (once)
    {
        const float4* src = (const float4*)g_WhsT;
        float4* dst = (float4*)sW;
        #pragma unroll 4
        for (int i = tid; i < 8192; i += THR) dst[i] = src[i];
    }
    for (int i = tid; i < 4096; i += THR) hcA[i] = 0.0f;   // zero initial state

    float  b2  = b_attn2[0];
    float4 w2v = ((const float4*)w_attn2)[l];

    // phase (a) mapping: warp w -> batchgrp bg (4 batches), k-group kg (32 k)
    int bgA = w >> 2, kgA = w & 3;
    int mA  = bgA * 4 + (l >> 3);          // batch this lane accumulates
    int kqA = kgA * 8 + (l & 7);           // k-quad this lane accumulates

    // phase (d) mapping
    int q = tid & 127, grp = tid >> 7, mb = grp * 4;
    float4 bgq = ((const float4*)g_bG)[q];
    ull bLo = pk2(bgq.x, bgq.y), bHi = pk2(bgq.z, bgq.w);

    const ulonglong2* Whh2 = (const ulonglong2*)g_WhhG;  // [j][64 pairs-of-2] at q
    const ulonglong2* Wih2 = (const ulonglong2*)g_WihG;
    const uint2* prb = (const uint2*)g_prex_bf + (size_t)(b0 + w) * 2048; // warp=m

    __syncthreads();

    for (int t = 0; t < TT; ++t) {
        float* hc  = (t & 1) ? hcB : hcA;
        float* hcn = (t & 1) ? hcA : hcB;

        // ---- (a) u[m][k] = sum_j [h|c][m][j] * WhsT[j][k]  (weights in smem)
        {
            const float4* hcm4 = (const float4*)(hc + mA * 256);
            const ulonglong2* sW2 = (const ulonglong2*)sW;   // [j][16]
            ull a0 = 0ull, a1 = 0ull;
            #pragma unroll 4
            for (int j4 = 0; j4 < 64; ++j4) {
                float4 hv = hcm4[j4];
                #pragma unroll
                for (int jj = 0; jj < 4; ++jj) {
                    ulonglong2 wv = sW2[(size_t)(j4 * 4 + jj) * 16 + kqA * 2 / 2
                                        ]; // placeholder, fixed below
                    (void)wv;
                    break;
                }
                // real body (indexing spelled out):
                {
                    float h0 = hv.x, h1 = hv.y, h2 = hv.z, h3 = hv.w;
                    ulonglong2 w0 = ((const ulonglong2*)sW)[(j4 * 4 + 0) * 32 + kqA];
                    ulonglong2 w1 = ((const ulonglong2*)sW)[(j4 * 4 + 1) * 32 + kqA];
                    ulonglong2 w2 = ((const ulonglong2*)sW)[(j4 * 4 + 2) * 32 + kqA];
                    ulonglong2 w3 = ((const ulonglong2*)sW)[(j4 * 4 + 3) * 32 + kqA];
                    ull p0 = pk2(h0, h0), p1 = pk2(h1, h1);
                    ull p2 = pk2(h2, h2), p3 = pk2(h3, h3);
                    fma2(a0, p0, w0.x); fma2(a1, p0, w0.y);
                    fma2(a0, p1, w1.x); fma2(a1, p1, w1.y);
                    fma2(a0, p2, w2.x); fma2(a1, p2, w2.y);
                    fma2(a0, p3, w3.x); fma2(a1, p3, w3.y);
                }
            }
            float2 r0 = up2(a0), r1 = up2(a1);
            ((float4*)(sU + mA * 128))[kqA] = make_float4(r0.x, r0.y, r1.x, r1.y);
        }
        __syncthreads();

        // ---- (b) partial e: warp=m; lane owns k-quad l; 3-level shuffle reduce
        {
            int m = w;
            float4 uv = ((const float4*)(sU + m * 128))[l];
            #pragma unroll 4
            for (int n = 0; n < NN; ++n) {
                uint2 pp = prb[n * 32 + l];   // 4 bf16 (k = l*4..l*4+3)
                float2 p01 = __bfloat1622float2(*(const __nv_bfloat162*)&pp.x);
                float2 p23 = __bfloat1622float2(*(const __nv_bfloat162*)&pp.y);
                float z0 = tanh_fast(p01.x + uv.x);
                float z1 = tanh_fast(p01.y + uv.y);
                float z2 = tanh_fast(p23.x + uv.z);
                float z3 = tanh_fast(p23.y + uv.w);
                float part = z0 * w2v.x + z1 * w2v.y + z2 * w2v.z + z3 * w2v.w;
                part += __shfl_xor_sync(0xffffffffu, part, 1);
                part += __shfl_xor_sync(0xffffffffu, part, 2);
                part += __shfl_xor_sync(0xffffffffu, part, 4);
                if ((l & 7) == 0) sE4[(m * 64 + n) * 4 + (l >> 3)] = part;
            }
        }
        __syncwarp();

        // ---- (c) finish e, softmax over n (64), x_tilde ; warp=m, 2 n per lane
        {
            int m = w;
            const float* e4 = sE4 + m * 256;
            float e0 = e4[l * 4 + 0] + e4[l * 4 + 1] + e4[l * 4 + 2] + e4[l * 4 + 3] + b2;
            int l2 = l + 32;
            float e1 = e4[l2 * 4 + 0] + e4[l2 * 4 + 1] + e4[l2 * 4 + 2] + e4[l2 * 4 + 3] + b2;
            float mx = fmaxf(e0, e1);
            #pragma unroll
            for (int o = 16; o > 0; o >>= 1)
                mx = fmaxf(mx, __shfl_xor_sync(0xffffffffu, mx, o));
            float x0 = __expf(e0 - mx), x1 = __expf(e1 - mx);
            float s = x0 + x1;
            #pragma unroll
            for (int o = 16; o > 0; o >>= 1)
                s += __shfl_xor_sync(0xffffffffu, s, o);
            float inv = 1.0f / s;
            const float* Xr = X + ((size_t)(b0 + m) * TT + t) * NN;
            sXT[m * 64 + l]      = x0 * inv * Xr[l];
            sXT[m * 64 + l + 32] = x1 * inv * Xr[l + 32];
        }
        __syncthreads();

        // ---- (d) gates for 4 batches mb..mb+3 at gate-quad q (f32x2 packed)
        ull aL0 = bLo, aH0 = bHi, aL1 = bLo, aH1 = bHi;
        ull aL2 = bLo, aH2 = bHi, aL3 = bLo, aH3 = bHi;
        {
            const float4* h40 = (const float4*)(hc + (mb + 0) * 256);
            const float4* h41 = (const float4*)(hc + (mb + 1) * 256);
            const float4* h42 = (const float4*)(hc + (mb + 2) * 256);
            const float4* h43 = (const float4*)(hc + (mb + 3) * 256);
            #pragma unroll 2
            for (int j4 = 0; j4 < 32; ++j4) {
                float4 v0 = h40[j4], v1 = h41[j4], v2 = h42[j4], v3 = h43[j4];
                #pragma unroll
                for (int jj = 0; jj < 4; ++jj) {
                    ulonglong2 wv = Whh2[(size_t)(j4 * 4 + jj) * 128 + q];
                    float f0 = (jj == 0) ? v0.x : (jj == 1) ? v0.y : (jj == 2) ? v0.z : v0.w;
                    float f1 = (jj == 0) ? v1.x : (jj == 1) ? v1.y : (jj == 2) ? v1.z : v1.w;
                    float f2 = (jj == 0) ? v2.x : (jj == 1) ? v2.y : (jj == 2) ? v2.z : v2.w;
                    float f3 = (jj == 0) ? v3.x : (jj == 1) ? v3.y : (jj == 2) ? v3.z : v3.w;
                    ull p0 = pk2(f0, f0), p1 = pk2(f1, f1);
                    ull p2 = pk2(f2, f2), p3 = pk2(f3, f3);
                    fma2(aL0, p0, wv.x); fma2(aH0, p0, wv.y);
                    fma2(aL1, p1, wv.x); fma2(aH1, p1, wv.y);
                    fma2(aL2, p2, wv.x); fma2(aH2, p2, wv.y);
                    fma2(aL3, p3, wv.x); fma2(aH3, p3, wv.y);
                }
            }
            const float4* x40 = (const float4*)(sXT + (mb + 0) * 64);
            const float4* x41 = (const float4*)(sXT + (mb + 1) * 64);
            const float4* x42 = (const float4*)(sXT + (mb + 2) * 64);
            const float4* x43 = (const float4*)(sXT + (mb + 3) * 64);
            #pragma unroll 2
            for (int n4 = 0; n4 < 16; ++n4) {
                float4 v0 = x40[n4], v1 = x41[n4], v2 = x42[n4], v3 = x43[n4];
                #pragma unroll
                for (int jj = 0; jj < 4; ++jj) {
                    ulonglong2 wv = Wih2[(size_t)(n4 * 4 + jj) * 128 + q];
                    float f0 = (jj == 0) ? v0.x : (jj == 1) ? v0.y : (jj == 2) ? v0.z : v0.w;
                    float f1 = (jj == 0) ? v1.x : (jj == 1) ? v1.y : (jj == 2) ? v1.z : v1.w;
                    float f2 = (jj == 0) ? v2.x : (jj == 1) ? v2.y : (jj == 2) ? v2.z : v2.w;
                    float f3 = (jj == 0) ? v3.x : (jj == 1) ? v3.y : (jj == 2) ? v3.z : v3.w;
                    ull p0 = pk2(f0, f0), p1 = pk2(f1, f1);
                    ull p2 = pk2(f2, f2), p3 = pk2(f3, f3);
                    fma2(aL0, p0, wv.x); fma2(aH0, p0, wv.y);
                    fma2(aL1, p1, wv.x); fma2(aH1, p1, wv.y);
                    fma2(aL2, p2, wv.x); fma2(aH2, p2, wv.y);
                    fma2(aL3, p3, wv.x); fma2(aH3, p3, wv.y);
                }
            }
        }

        // ---- (e) LSTM pointwise update -> double-buffered state + output
        #pragma unroll
        for (int mm = 0; mm < 4; ++mm) {
            ull aL = (mm == 0) ? aL0 : (mm == 1) ? aL1 : (mm == 2) ? aL2 : aL3;
            ull aH = (mm == 0) ? aH0 : (mm == 1) ? aH1 : (mm == 2) ? aH2 : aH3;
            float2 gif = up2(aL);   // i, f
            float2 ggo = up2(aH);   // g, o
            float iv = sigmoid_f(gif.x);
            float fv = sigmoid_f(gif.y);
            float gv = tanhf(ggo.x);
            float ov = sigmoid_f(ggo.y);
            float cold = hc[(mb + mm) * 256 + 128 + q];
            float c2 = fv * cold + iv * gv;
            float hn = ov * tanhf(c2);
            hcn[(mb + mm) * 256 + q]       = hn;
            hcn[(mb + mm) * 256 + 128 + q] = c2;
            out[((size_t)(b0 + mb + mm) * TT + t) * HH + q] = hn;
        }
        __syncthreads();   // hcn visible for next step's (a)/(d)
    }
}

// ---------------- launch ------------------------------------------------------
extern "C" void kernel_launch(void* const* d_in, const int* in_sizes, int n_in,
                              void* d_out, int out_size) {
    const float* X       = (const float*)d_in[0];
    const float* W_attn1 = (const float*)d_in[1];
    const float* b_attn1 = (const float*)d_in[2];
    const float* w_attn2 = (const float*)d_in[3];
    const float* b_attn2 = (const float*)d_in[4];
    const float* W_ih    = (const float*)d_in[5];
    const float* W_hh    = (const float*)d_in[6];
    const float* b_ih    = (const float*)d_in[7];
    const float* b_hh    = (const float*)d_in[8];
    float* out = (float*)d_out;

    cudaFuncSetAttribute(rnn_kernel, cudaFuncAttributeMaxDynamicSharedMemorySize,
                         SMEM_FLOATS * (int)sizeof(float));

    prep_kernel<<<64, 256>>>(W_attn1, W_ih, W_hh, b_ih, b_hh);
    prex_kernel<<<BB, 256>>>(X, b_attn1);
    rnn_kernel<<<BB / MM, THR, SMEM_FLOATS * sizeof(float)>>>(X, w_attn2, b_attn2, out);
}

// round 6
// speedup vs baseline: 1.6429x; 1.1142x over previous
#include <cuda_runtime.h>
#include <cuda_bf16.h>

#define BB 2048
#define TT 128
#define NN 64
#define HH 128
#define G4 512   // 4*H
#define THR 512  // threads per CTA (16 warps)
#define NFULL 124 // CTAs with 14 batches; rest have 13
#define HCP 264   // padded hc row stride (floats)
#define SUP 132   // padded sU row stride (floats)

// ---------------- device scratch (allocation-free: __device__ globals) -------
__device__ __align__(16) __nv_bfloat16 g_prex_bf[(size_t)BB * NN * HH]; // [b][n][k] bf16
__device__ __align__(16) float g_WhsT[256 * HH];   // [j][k] j<128: W1_h col, j>=128: W1_s col
__device__ __align__(16) float g_W1xT[TT * HH];    // [t][k]
__device__ __align__(16) float g_WihG[NN * G4];    // [n][q*4+gate]
__device__ __align__(16) float g_WhhG[HH * G4];    // [j][q*4+gate]
__device__ __align__(16) float g_bG[G4];           // [q*4+gate]

typedef unsigned long long ull;

__device__ __forceinline__ ull pk2(float a, float b) {
    ull r; asm("mov.b64 %0,{%1,%2};" : "=l"(r) : "f"(a), "f"(b)); return r;
}
__device__ __forceinline__ void fma2(ull& d, ull a, ull b) {
    asm("fma.rn.f32x2 %0, %1, %2, %0;" : "+l"(d) : "l"(a), "l"(b));
}
__device__ __forceinline__ float2 up2(ull v) {
    float2 r; asm("mov.b64 {%0,%1},%2;" : "=f"(r.x), "=f"(r.y) : "l"(v)); return r;
}
__device__ __forceinline__ float tanh_fast(float x) {
    float y; asm("tanh.approx.f32 %0, %1;" : "=f"(y) : "f"(x)); return y;
}
__device__ __forceinline__ float sigmoid_f(float x) {
    return 1.0f / (1.0f + __expf(-x));
}
__device__ __forceinline__ void fma4(float4& a, float s, const float4 w) {
    a.x = fmaf(s, w.x, a.x); a.y = fmaf(s, w.y, a.y);
    a.z = fmaf(s, w.z, a.z); a.w = fmaf(s, w.w, a.w);
}

// ---------------- kernel 0: weight layout prep --------------------------------
__global__ void prep_kernel(const float* __restrict__ W_attn1,
                            const float* __restrict__ W_ih,
                            const float* __restrict__ W_hh,
                            const float* __restrict__ b_ih,
                            const float* __restrict__ b_hh)
{
    int tid = blockIdx.x * blockDim.x + threadIdx.x;
    int nt  = gridDim.x * blockDim.x;
    for (int i = tid; i < 256 * HH; i += nt) {
        int j = i >> 7, k = i & 127;
        g_WhsT[i] = W_attn1[k * 384 + j];
    }
    for (int i = tid; i < TT * HH; i += nt) {
        int t = i >> 7, k = i & 127;
        g_W1xT[i] = W_attn1[k * 384 + 256 + t];
    }
    for (int i = tid; i < NN * G4; i += nt) {
        int n = i >> 9, r = i & 511, q = r >> 2, g = r & 3;
        g_WihG[i] = W_ih[(g * HH + q) * NN + n];
    }
    for (int i = tid; i < HH * G4; i += nt) {
        int j = i >> 9, r = i & 511, q = r >> 2, g = r & 3;
        g_WhhG[i] = W_hh[(g * HH + q) * HH + j];
    }
    for (int i = tid; i < G4; i += nt) {
        int q = i >> 2, g = i & 3;
        g_bG[i] = b_ih[g * HH + q] + b_hh[g * HH + q];
    }
}

// ---------------- kernel 1: pre_x[b][n][k] = sum_t X[b][t][n]*W1x[k][t] + b1[k]
__global__ __launch_bounds__(256) void prex_kernel(const float* __restrict__ X,
                                                   const float* __restrict__ b_attn1)
{
    __shared__ float sX[TT * NN];   // 32 KB
    int b = blockIdx.x;
    int tid = threadIdx.x;
    const float* Xb = X + (size_t)b * TT * NN;
    for (int i = tid; i < TT * NN; i += 256) sX[i] = Xb[i];
    __syncthreads();

    const float4* W4  = (const float4*)g_W1xT;     // [t][32 quads]
    const float4* b14 = (const float4*)b_attn1;
    uint2* out2 = (uint2*)(g_prex_bf + (size_t)b * NN * HH);

    for (int qi = tid; qi < NN * 32; qi += 256) {
        int n = qi >> 5, kq = qi & 31;
        float4 acc = b14[kq];
        #pragma unroll 4
        for (int t = 0; t < TT; ++t) {
            float x = sX[t * NN + n];
            fma4(acc, x, W4[t * 32 + kq]);
        }
        __nv_bfloat162 c0 = __floats2bfloat162_rn(acc.x, acc.y);
        __nv_bfloat162 c1 = __floats2bfloat162_rn(acc.z, acc.w);
        uint2 st;
        st.x = *(unsigned*)&c0;
        st.y = *(unsigned*)&c1;
        out2[n * 32 + kq] = st;
    }
}

// ---------------- kernel 2: the recurrence ------------------------------------
// dynamic smem (floats): sW 32768 | hcA 16*264=4224 | hcB 4224 | sU 16*132=2112 | sXT 1024
#define SMEM_FLOATS (32768 + 4224 + 4224 + 2112 + 1024)

__global__ __launch_bounds__(THR, 1) void rnn_kernel(
    const float* __restrict__ X,
    const float* __restrict__ w_attn2,
    const float* __restrict__ b_attn2,
    float* __restrict__ out)
{
    extern __shared__ float smem[];
    float* sW  = smem;
    float* hcA = sW + 32768;
    float* hcB = hcA + 4224;
    float* sU  = hcB + 4224;
    float* sXT = sU + 2112;

    int tid = threadIdx.x;
    int l = tid & 31;
    int w = tid >> 5;                 // warp id == m for phases (b)(c)
    int cta = blockIdx.x;
    int cnt  = (cta < NFULL) ? 14 : 13;
    size_t b0 = (cta < NFULL) ? (size_t)cta * 14
                              : (size_t)(NFULL * 14 + (cta - NFULL) * 13);

    // stage W_attn1^T into smem (once)
    {
        const float4* src = (const float4*)g_WhsT;
        float4* dst = (float4*)sW;
        #pragma unroll 4
        for (int i = tid; i < 8192; i += THR) dst[i] = src[i];
    }
    for (int i = tid; i < 8448; i += THR) hcA[i] = 0.0f;   // zero both hc buffers
    for (int i = tid; i < 1024; i += THR) sXT[i] = 0.0f;   // keep invalid rows finite

    float b2 = b_attn2[0];

    // phase (a) mapping: warp w -> batchgrp (w>>2, 4 batches), k-group (w&3)
    int mA  = (w >> 2) * 4 + (l >> 3);     // batch this lane accumulates
    int kqA = (w & 3) * 8 + (l & 7);       // k-quad (float4 index 0..31)

    // phase (d) mapping
    int q = tid & 127, grp = tid >> 7, mb = grp * 4;
    float4 bgq = ((const float4*)g_bG)[q];
    ull bLo = pk2(bgq.x, bgq.y), bHi = pk2(bgq.z, bgq.w);

    const ulonglong2* Whh2 = (const ulonglong2*)g_WhhG;
    const ulonglong2* Wih2 = (const ulonglong2*)g_WihG;
    int mw = (w < cnt) ? w : 0;
    const uint2* prb = (const uint2*)g_prex_bf + (size_t)(b0 + mw) * 2048;

    __syncthreads();

    for (int t = 0; t < TT; ++t) {
        float* hc  = (t & 1) ? hcB : hcA;
        float* hcn = (t & 1) ? hcA : hcB;

        // ---- (a) u[m][k] = sum_j [h|c][m][j] * WhsT[j][k]  (weights in smem)
        {
            const float4* hcm4 = (const float4*)(hc + mA * HCP);
            const ulonglong2* sW2 = (const ulonglong2*)sW;   // [j][32]
            ull a0 = 0ull, a1 = 0ull;
            #pragma unroll 4
            for (int j4 = 0; j4 < 64; ++j4) {
                float4 hv = hcm4[j4];
                ulonglong2 w0 = sW2[(j4 * 4 + 0) * 32 + kqA];
                ulonglong2 w1 = sW2[(j4 * 4 + 1) * 32 + kqA];
                ulonglong2 w2 = sW2[(j4 * 4 + 2) * 32 + kqA];
                ulonglong2 w3 = sW2[(j4 * 4 + 3) * 32 + kqA];
                ull p0 = pk2(hv.x, hv.x), p1 = pk2(hv.y, hv.y);
                ull p2 = pk2(hv.z, hv.z), p3 = pk2(hv.w, hv.w);
                fma2(a0, p0, w0.x); fma2(a1, p0, w0.y);
                fma2(a0, p1, w1.x); fma2(a1, p1, w1.y);
                fma2(a0, p2, w2.x); fma2(a1, p2, w2.y);
                fma2(a0, p3, w3.x); fma2(a1, p3, w3.y);
            }
            float2 r0 = up2(a0), r1 = up2(a1);
            ((float4*)(sU + mA * SUP))[kqA] = make_float4(r0.x, r0.y, r1.x, r1.y);
        }
        __syncthreads();

        // ---- (b)+(c): e, softmax, x_tilde. warp=m; lane ends with e[n=l].
        if (w < cnt) {
            int kq = l & 7;
            const float4* sUr = (const float4*)(sU + w * SUP);
            float4 u0 = sUr[kq], u1 = sUr[kq + 8], u2 = sUr[kq + 16], u3 = sUr[kq + 24];
            const float4* w24 = (const float4*)w_attn2;
            float4 wA = w24[kq], wB = w24[kq + 8], wC = w24[kq + 16], wD = w24[kq + 24];
            float ee[2];
            #pragma unroll
            for (int p = 0; p < 2; ++p) {
                int nb = p * 32 + (l & 24);     // this lane's 8-n block
                const uint2* pp = prb + (size_t)nb * 32 + kq;
                uint2 c0 = pp[0], c1 = pp[8], c2 = pp[16], c3 = pp[24];
                float v[8];
                #pragma unroll
                for (int i = 0; i < 8; ++i) {
                    const uint2* pn = prb + (size_t)(nb + ((i + 1) & 7)) * 32 + kq;
                    uint2 n0 = pn[0], n1 = pn[8], n2 = pn[16], n3 = pn[24];
                    float s;
                    {
                        float2 a01 = __bfloat1622float2(*(const __nv_bfloat162*)&c0.x);
                        float2 a23 = __bfloat1622float2(*(const __nv_bfloat162*)&c0.y);
                        float z0 = tanh_fast(a01.x + u0.x);
                        float z1 = tanh_fast(a01.y + u0.y);
                        float z2 = tanh_fast(a23.x + u0.z);
                        float z3 = tanh_fast(a23.y + u0.w);
                        s = z0 * wA.x;
                        s = fmaf(z1, wA.y, s); s = fmaf(z2, wA.z, s); s = fmaf(z3, wA.w, s);
                    }
                    {
                        float2 a01 = __bfloat1622float2(*(const __nv_bfloat162*)&c1.x);
                        float2 a23 = __bfloat1622float2(*(const __nv_bfloat162*)&c1.y);
                        s = fmaf(tanh_fast(a01.x + u1.x), wB.x, s);
                        s = fmaf(tanh_fast(a01.y + u1.y), wB.y, s);
                        s = fmaf(tanh_fast(a23.x + u1.z), wB.z, s);
                        s = fmaf(tanh_fast(a23.y + u1.w), wB.w, s);
                    }
                    {
                        float2 a01 = __bfloat1622float2(*(const __nv_bfloat162*)&c2.x);
                        float2 a23 = __bfloat1622float2(*(const __nv_bfloat162*)&c2.y);
                        s = fmaf(tanh_fast(a01.x + u2.x), wC.x, s);
                        s = fmaf(tanh_fast(a01.y + u2.y), wC.y, s);
                        s = fmaf(tanh_fast(a23.x + u2.z), wC.z, s);
                        s = fmaf(tanh_fast(a23.y + u2.w), wC.w, s);
                    }
                    {
                        float2 a01 = __bfloat1622float2(*(const __nv_bfloat162*)&c3.x);
                        float2 a23 = __bfloat1622float2(*(const __nv_bfloat162*)&c3.y);
                        s = fmaf(tanh_fast(a01.x + u3.x), wD.x, s);
                        s = fmaf(tanh_fast(a01.y + u3.y), wD.y, s);
                        s = fmaf(tanh_fast(a23.x + u3.z), wD.z, s);
                        s = fmaf(tanh_fast(a23.y + u3.w), wD.w, s);
                    }
                    v[i] = s;
                    c0 = n0; c1 = n1; c2 = n2; c3 = n3;
                }
                // 8-lane butterfly transpose-reduce: lane ends with sum for i = l&7
                bool h1 = l & 1, h2 = l & 2, h4 = l & 4;
                float s0 = h1 ? v[0] : v[1];
                float a0 = (h1 ? v[1] : v[0]) + __shfl_xor_sync(0xffffffffu, s0, 1);
                float s1 = h1 ? v[2] : v[3];
                float a1 = (h1 ? v[3] : v[2]) + __shfl_xor_sync(0xffffffffu, s1, 1);
                float s2 = h1 ? v[4] : v[5];
                float a2 = (h1 ? v[5] : v[4]) + __shfl_xor_sync(0xffffffffu, s2, 1);
                float s3 = h1 ? v[6] : v[7];
                float a3 = (h1 ? v[7] : v[6]) + __shfl_xor_sync(0xffffffffu, s3, 1);
                float t0 = h2 ? a0 : a1;
                float bb0 = (h2 ? a1 : a0) + __shfl_xor_sync(0xffffffffu, t0, 2);
                float t1 = h2 ? a2 : a3;
                float bb1 = (h2 ? a3 : a2) + __shfl_xor_sync(0xffffffffu, t1, 2);
                float t2 = h4 ? bb0 : bb1;
                float ev = (h4 ? bb1 : bb0) + __shfl_xor_sync(0xffffffffu, t2, 4);
                ee[p] = ev + b2;           // e for n = p*32 + l
            }
            // softmax over 64 n + x_tilde
            float e0 = ee[0], e1 = ee[1];
            float mx = fmaxf(e0, e1);
            #pragma unroll
            for (int o = 16; o > 0; o >>= 1)
                mx = fmaxf(mx, __shfl_xor_sync(0xffffffffu, mx, o));
            float x0 = __expf(e0 - mx), x1 = __expf(e1 - mx);
            float sm = x0 + x1;
            #pragma unroll
            for (int o = 16; o > 0; o >>= 1)
                sm += __shfl_xor_sync(0xffffffffu, sm, o);
            float inv = 1.0f / sm;
            const float* Xr = X + ((size_t)(b0 + w) * TT + t) * NN;
            sXT[w * 64 + l]      = x0 * inv * Xr[l];
            sXT[w * 64 + l + 32] = x1 * inv * Xr[l + 32];
        }
        __syncthreads();

        // ---- (d) gates for 4 batches mb..mb+3 at gate-quad q (f32x2, prefetched)
        ull aL0 = bLo, aH0 = bHi, aL1 = bLo, aH1 = bHi;
        ull aL2 = bLo, aH2 = bHi, aL3 = bLo, aH3 = bHi;
        {
            const float4* h40 = (const float4*)(hc + (mb + 0) * HCP);
            const float4* h41 = (const float4*)(hc + (mb + 1) * HCP);
            const float4* h42 = (const float4*)(hc + (mb + 2) * HCP);
            const float4* h43 = (const float4*)(hc + (mb + 3) * HCP);
            const ulonglong2* Wh = Whh2 + q;
            ulonglong2 wq0 = Wh[0], wq1 = Wh[128], wq2 = Wh[256], wq3 = Wh[384];
            #pragma unroll 4
            for (int j4 = 0; j4 < 32; ++j4) {
                int nj = ((j4 + 1) & 31) * 4;
                ulonglong2 f0 = Wh[(size_t)(nj + 0) * 128];
                ulonglong2 f1 = Wh[(size_t)(nj + 1) * 128];
                ulonglong2 f2 = Wh[(size_t)(nj + 2) * 128];
                ulonglong2 f3 = Wh[(size_t)(nj + 3) * 128];
                float4 v0 = h40[j4], v1 = h41[j4], v2 = h42[j4], v3 = h43[j4];
                ull p0, p1, p2, p3;
                p0 = pk2(v0.x, v0.x); p1 = pk2(v1.x, v1.x); p2 = pk2(v2.x, v2.x); p3 = pk2(v3.x, v3.x);
                fma2(aL0, p0, wq0.x); fma2(aH0, p0, wq0.y);
                fma2(aL1, p1, wq0.x); fma2(aH1, p1, wq0.y);
                fma2(aL2, p2, wq0.x); fma2(aH2, p2, wq0.y);
                fma2(aL3, p3, wq0.x); fma2(aH3, p3, wq0.y);
                p0 = pk2(v0.y, v0.y); p1 = pk2(v1.y, v1.y); p2 = pk2(v2.y, v2.y); p3 = pk2(v3.y, v3.y);
                fma2(aL0, p0, wq1.x); fma2(aH0, p0, wq1.y);
                fma2(aL1, p1, wq1.x); fma2(aH1, p1, wq1.y);
                fma2(aL2, p2, wq1.x); fma2(aH2, p2, wq1.y);
                fma2(aL3, p3, wq1.x); fma2(aH3, p3, wq1.y);
                p0 = pk2(v0.z, v0.z); p1 = pk2(v1.z, v1.z); p2 = pk2(v2.z, v2.z); p3 = pk2(v3.z, v3.z);
                fma2(aL0, p0, wq2.x); fma2(aH0, p0, wq2.y);
                fma2(aL1, p1, wq2.x); fma2(aH1, p1, wq2.y);
                fma2(aL2, p2, wq2.x); fma2(aH2, p2, wq2.y);
                fma2(aL3, p3, wq2.x); fma2(aH3, p3, wq2.y);
                p0 = pk2(v0.w, v0.w); p1 = pk2(v1.w, v1.w); p2 = pk2(v2.w, v2.w); p3 = pk2(v3.w, v3.w);
                fma2(aL0, p0, wq3.x); fma2(aH0, p0, wq3.y);
                fma2(aL1, p1, wq3.x); fma2(aH1, p1, wq3.y);
                fma2(aL2, p2, wq3.x); fma2(aH2, p2, wq3.y);
                fma2(aL3, p3, wq3.x); fma2(aH3, p3, wq3.y);
                wq0 = f0; wq1 = f1; wq2 = f2; wq3 = f3;
            }
            const float4* x40 = (const float4*)(sXT + (mb + 0) * 64);
            const float4* x41 = (const float4*)(sXT + (mb + 1) * 64);
            const float4* x42 = (const float4*)(sXT + (mb + 2) * 64);
            const float4* x43 = (const float4*)(sXT + (mb + 3) * 64);
            const ulonglong2* Wi = Wih2 + q;
            wq0 = Wi[0]; wq1 = Wi[128]; wq2 = Wi[256]; wq3 = Wi[384];
            #pragma unroll 4
            for (int n4 = 0; n4 < 16; ++n4) {
                int nj = ((n4 + 1) & 15) * 4;
                ulonglong2 f0 = Wi[(size_t)(nj + 0) * 128];
                ulonglong2 f1 = Wi[(size_t)(nj + 1) * 128];
                ulonglong2 f2 = Wi[(size_t)(nj + 2) * 128];
                ulonglong2 f3 = Wi[(size_t)(nj + 3) * 128];
                float4 v0 = x40[n4], v1 = x41[n4], v2 = x42[n4], v3 = x43[n4];
                ull p0, p1, p2, p3;
                p0 = pk2(v0.x, v0.x); p1 = pk2(v1.x, v1.x); p2 = pk2(v2.x, v2.x); p3 = pk2(v3.x, v3.x);
                fma2(aL0, p0, wq0.x); fma2(aH0, p0, wq0.y);
                fma2(aL1, p1, wq0.x); fma2(aH1, p1, wq0.y);
                fma2(aL2, p2, wq0.x); fma2(aH2, p2, wq0.y);
                fma2(aL3, p3, wq0.x); fma2(aH3, p3, wq0.y);
                p0 = pk2(v0.y, v0.y); p1 = pk2(v1.y, v1.y); p2 = pk2(v2.y, v2.y); p3 = pk2(v3.y, v3.y);
                fma2(aL0, p0, wq1.x); fma2(aH0, p0, wq1.y);
                fma2(aL1, p1, wq1.x); fma2(aH1, p1, wq1.y);
                fma2(aL2, p2, wq1.x); fma2(aH2, p2, wq1.y);
                fma2(aL3, p3, wq1.x); fma2(aH3, p3, wq1.y);
                p0 = pk2(v0.z, v0.z); p1 = pk2(v1.z, v1.z); p2 = pk2(v2.z, v2.z); p3 = pk2(v3.z, v3.z);
                fma2(aL0, p0, wq2.x); fma2(aH0, p0, wq2.y);
                fma2(aL1, p1, wq2.x); fma2(aH1, p1, wq2.y);
                fma2(aL2, p2, wq2.x); fma2(aH2, p2, wq2.y);
                fma2(aL3, p3, wq2.x); fma2(aH3, p3, wq2.y);
                p0 = pk2(v0.w, v0.w); p1 = pk2(v1.w, v1.w); p2 = pk2(v2.w, v2.w); p3 = pk2(v3.w, v3.w);
                fma2(aL0, p0, wq3.x); fma2(aH0, p0, wq3.y);
                fma2(aL1, p1, wq3.x); fma2(aH1, p1, wq3.y);
                fma2(aL2, p2, wq3.x); fma2(aH2, p2, wq3.y);
                fma2(aL3, p3, wq3.x); fma2(aH3, p3, wq3.y);
                wq0 = f0; wq1 = f1; wq2 = f2; wq3 = f3;
            }
        }

        // ---- (e) LSTM pointwise update -> double-buffered state + output
        #pragma unroll
        for (int mm = 0; mm < 4; ++mm) {
            if (mb + mm < cnt) {
                ull aL = (mm == 0) ? aL0 : (mm == 1) ? aL1 : (mm == 2) ? aL2 : aL3;
                ull aH = (mm == 0) ? aH0 : (mm == 1) ? aH1 : (mm == 2) ? aH2 : aH3;
                float2 gif = up2(aL);   // i, f
                float2 ggo = up2(aH);   // g, o
                float iv = sigmoid_f(gif.x);
                float fv = sigmoid_f(gif.y);
                float gv = tanhf(ggo.x);
                float ov = sigmoid_f(ggo.y);
                float cold = hc[(mb + mm) * HCP + 128 + q];
                float c2 = fv * cold + iv * gv;
                float hn = ov * tanhf(c2);
                hcn[(mb + mm) * HCP + q]       = hn;
                hcn[(mb + mm) * HCP + 128 + q] = c2;
                out[((size_t)(b0 + mb + mm) * TT + t) * HH + q] = hn;
            }
        }
        __syncthreads();   // hcn + sXT consumption complete before next step
    }
}

// ---------------- launch ------------------------------------------------------
extern "C" void kernel_launch(void* const* d_in, const int* in_sizes, int n_in,
                              void* d_out, int out_size) {
    const float* X       = (const float*)d_in[0];
    const float* W_attn1 = (const float*)d_in[1];
    const float* b_attn1 = (const float*)d_in[2];
    const float* w_attn2 = (const float*)d_in[3];
    const float* b_attn2 = (const float*)d_in[4];
    const float* W_ih    = (const float*)d_in[5];
    const float* W_hh    = (const float*)d_in[6];
    const float* b_ih    = (const float*)d_in[7];
    const float* b_hh    = (const float*)d_in[8];
    float* out = (float*)d_out;

    cudaFuncSetAttribute(rnn_kernel, cudaFuncAttributeMaxDynamicSharedMemorySize,
                         SMEM_FLOATS * (int)sizeof(float));

    prep_kernel<<<64, 256>>>(W_attn1, W_ih, W_hh, b_ih, b_hh);
    prex_kernel<<<BB, 256>>>(X, b_attn1);
    rnn_kernel<<<148, THR, SMEM_FLOATS * sizeof(float)>>>(X, w_attn2, b_attn2, out);
}